// round 1
// baseline (speedup 1.0000x reference)
#include <cuda_runtime.h>
#include <math.h>

#define NB_MAX 400
#define WKER 0.05f
#define INV_WKER 20.0f
#define CUT 0.30f
#define GNORM 7.9788456080f   // 1/(0.05*sqrt(2*pi))

__device__ float g_hist[NB_MAX];
__device__ float g_cinv[9];
__device__ float g_vol;

// ---------------------------------------------------------------------------
// Kernel 0: zero the histogram, compute cell inverse + |det|
// ---------------------------------------------------------------------------
__global__ void setup_kernel(const float* __restrict__ cell, int nb) {
    int t = threadIdx.x;
    for (int k = t; k < nb; k += blockDim.x) g_hist[k] = 0.0f;
    if (t == 0) {
        float m[9];
        #pragma unroll
        for (int i = 0; i < 9; i++) m[i] = cell[i];
        float c00 =  (m[4]*m[8] - m[5]*m[7]);
        float c01 = -(m[3]*m[8] - m[5]*m[6]);
        float c02 =  (m[3]*m[7] - m[4]*m[6]);
        float det = m[0]*c00 + m[1]*c01 + m[2]*c02;
        float id  = 1.0f / det;
        g_cinv[0] =  c00 * id;
        g_cinv[1] = -(m[1]*m[8] - m[2]*m[7]) * id;
        g_cinv[2] =  (m[1]*m[5] - m[2]*m[4]) * id;
        g_cinv[3] =  c01 * id;
        g_cinv[4] =  (m[0]*m[8] - m[2]*m[6]) * id;
        g_cinv[5] = -(m[0]*m[5] - m[2]*m[3]) * id;
        g_cinv[6] =  c02 * id;
        g_cinv[7] = -(m[0]*m[7] - m[1]*m[6]) * id;
        g_cinv[8] =  (m[0]*m[4] - m[1]*m[3]) * id;
        g_vol = fabsf(det);
    }
}

// ---------------------------------------------------------------------------
// Kernel 1: pair distances (minimum image) + truncated-Gaussian KDE histogram
// Block b owns rows i=b and i=N-1-b  (each block handles exactly N-1 pairs).
// ---------------------------------------------------------------------------
__global__ void __launch_bounds__(256)
hist_kernel(const float* __restrict__ pos, const float* __restrict__ cell,
            const float* __restrict__ rb, int N, int nb) {
    __shared__ float s_hist[NB_MAX];
    __shared__ float s_r[NB_MAX];
    __shared__ float s_ci[9];
    __shared__ float s_c[9];
    int t = threadIdx.x;

    for (int k = t; k < nb; k += blockDim.x) {
        s_hist[k] = 0.0f;
        s_r[k]    = rb[k];
    }
    if (t < 9) { s_ci[t] = g_cinv[t]; s_c[t] = cell[t]; }
    __syncthreads();

    const float r0     = s_r[0];
    const float dr     = s_r[1] - s_r[0];
    const float inv_dr = 1.0f / dr;
    const float minb   = s_r[0]      - 3.0f * WKER;
    const float maxb   = s_r[nb - 1] + 3.0f * WKER;

    #pragma unroll
    for (int half = 0; half < 2; half++) {
        int i = (half == 0) ? (int)blockIdx.x : (N - 1 - (int)blockIdx.x);
        if (i < 0 || i >= N - 1) continue;
        float xi = pos[3*i + 0], yi = pos[3*i + 1], zi = pos[3*i + 2];

        for (int j = i + 1 + t; j < N; j += blockDim.x) {
            float dx = pos[3*j + 0] - xi;
            float dy = pos[3*j + 1] - yi;
            float dz = pos[3*j + 2] - zi;
            // fractional coords: diff @ cell_inv
            float fx = dx*s_ci[0] + dy*s_ci[3] + dz*s_ci[6];
            float fy = dx*s_ci[1] + dy*s_ci[4] + dz*s_ci[7];
            float fz = dx*s_ci[2] + dy*s_ci[5] + dz*s_ci[8];
            fx -= rintf(fx); fy -= rintf(fy); fz -= rintf(fz);
            // back to cartesian: frac @ cell
            float mx = fx*s_c[0] + fy*s_c[3] + fz*s_c[6];
            float my = fx*s_c[1] + fy*s_c[4] + fz*s_c[7];
            float mz = fx*s_c[2] + fy*s_c[5] + fz*s_c[8];
            float d  = sqrtf(mx*mx + my*my + mz*mz + 1e-10f);

            // exact window mask (matches reference in_win)
            if (d <= minb || d >= maxb) continue;

            int klo = (int)ceilf ((d - CUT - r0) * inv_dr);
            int khi = (int)floorf((d + CUT - r0) * inv_dr);
            klo = klo < 0 ? 0 : klo;
            khi = khi > nb - 1 ? nb - 1 : khi;
            for (int k = klo; k <= khi; k++) {
                float u = (s_r[k] - d) * INV_WKER;
                atomicAdd(&s_hist[k], GNORM * __expf(-0.5f * u * u));
            }
        }
    }
    __syncthreads();
    for (int k = t; k < nb; k += blockDim.x) {
        float v = s_hist[k];
        if (v != 0.0f) atomicAdd(&g_hist[k], v);
    }
}

// ---------------------------------------------------------------------------
// Kernel 2: G(r) = coeff * (vol/n_pairs * hist / (4 pi r^2) - 1)
// ---------------------------------------------------------------------------
__global__ void g_kernel(const float* __restrict__ rb, float* __restrict__ out,
                         int nb, float n_pairs) {
    int k = blockIdx.x * blockDim.x + threadIdx.x;
    if (k >= nb) return;
    float r   = rb[k];
    float gp  = (g_vol / n_pairs) * g_hist[k] / (4.0f * 3.14159265358979f * r * r);
    float coeff = 5.803f * 5.803f * 0.01f;
    out[k] = coeff * (gp - 1.0f);
}

// ---------------------------------------------------------------------------
// Kernel 3: S(Q) = 1 + 4 pi rho * trapz( r G(r) sin(Qr)/(Q+1e-10), r )
//           F(Q) = Q (S(Q) - 1)
// One block per Q bin; double accumulation for the trapz.
// ---------------------------------------------------------------------------
__global__ void __launch_bounds__(128)
sf_kernel(const float* __restrict__ rb, const float* __restrict__ qb,
          float* __restrict__ out, int nb, int N) {
    __shared__ double s_red[128];
    int q = blockIdx.x;
    int t = threadIdx.x;
    double Q    = (double)qb[q];
    double invq = 1.0 / (Q + 1e-10);
    const float* G = out;  // first nb entries already hold G(r)

    double acc = 0.0;
    for (int k = t; k < nb - 1; k += blockDim.x) {
        double r1 = (double)rb[k],     r2 = (double)rb[k + 1];
        double y1 = r1 * (double)G[k]     * sin(Q * r1) * invq;
        double y2 = r2 * (double)G[k + 1] * sin(Q * r2) * invq;
        acc += 0.5 * (y1 + y2) * (r2 - r1);
    }
    s_red[t] = acc;
    __syncthreads();
    for (int s = 64; s > 0; s >>= 1) {
        if (t < s) s_red[t] += s_red[t + s];
        __syncthreads();
    }
    if (t == 0) {
        double rho = (double)N / (double)g_vol;
        double S   = 1.0 + 4.0 * 3.14159265358979323846 * rho * s_red[0];
        out[nb + q]     = (float)S;
        out[2 * nb + q] = qb[q] * ((float)S - 1.0f);
    }
}

// ---------------------------------------------------------------------------
extern "C" void kernel_launch(void* const* d_in, const int* in_sizes, int n_in,
                              void* d_out, int out_size) {
    const float* pos  = (const float*)d_in[0];
    const float* cell = (const float*)d_in[1];
    const float* rb   = (const float*)d_in[2];
    const float* qb   = (const float*)d_in[3];
    float* out = (float*)d_out;

    int N  = in_sizes[0] / 3;
    int nb = in_sizes[2];

    setup_kernel<<<1, 512>>>(cell, nb);
    hist_kernel<<<(N + 1) / 2, 256>>>(pos, cell, rb, N, nb);
    float n_pairs = 0.5f * (float)N * (float)(N - 1);
    g_kernel<<<(nb + 127) / 128, 128>>>(rb, out, nb, n_pairs);
    sf_kernel<<<nb, 128>>>(rb, qb, out, nb, N);
}

// round 5
// speedup vs baseline: 1.9743x; 1.9743x over previous
#include <cuda_runtime.h>
#include <math.h>

#define NB_MAX 400
#define NMAX   1024
#define WKER   0.05f
#define INV_WKER 20.0f
#define CUT    0.225f          // 4.5 sigma truncation
#define GNORM  7.9788456080f   // 1/(0.05*sqrt(2*pi))
#define PI_F   3.14159265358979f

__device__ float g_hist[NB_MAX];
__device__ float g_cinv[9];
__device__ float g_vol;
__device__ int   g_diag;

// ---------------------------------------------------------------------------
// Kernel 0: zero histogram, compute cell inverse + |det| + diagonality flag
// ---------------------------------------------------------------------------
__global__ void setup_kernel(const float* __restrict__ cell, int nb) {
    int t = threadIdx.x;
    for (int k = t; k < nb; k += blockDim.x) g_hist[k] = 0.0f;
    if (t == 0) {
        float m[9];
        #pragma unroll
        for (int i = 0; i < 9; i++) m[i] = cell[i];
        float c00 =  (m[4]*m[8] - m[5]*m[7]);
        float c01 = -(m[3]*m[8] - m[5]*m[6]);
        float c02 =  (m[3]*m[7] - m[4]*m[6]);
        float det = m[0]*c00 + m[1]*c01 + m[2]*c02;
        float id  = 1.0f / det;
        g_cinv[0] =  c00 * id;
        g_cinv[1] = -(m[1]*m[8] - m[2]*m[7]) * id;
        g_cinv[2] =  (m[1]*m[5] - m[2]*m[4]) * id;
        g_cinv[3] =  c01 * id;
        g_cinv[4] =  (m[0]*m[8] - m[2]*m[6]) * id;
        g_cinv[5] = -(m[0]*m[5] - m[2]*m[3]) * id;
        g_cinv[6] =  c02 * id;
        g_cinv[7] = -(m[0]*m[7] - m[1]*m[6]) * id;
        g_cinv[8] =  (m[0]*m[4] - m[1]*m[3]) * id;
        g_vol = fabsf(det);
        g_diag = (m[1]==0.f && m[2]==0.f && m[3]==0.f &&
                  m[5]==0.f && m[6]==0.f && m[7]==0.f) ? 1 : 0;
    }
}

// ---------------------------------------------------------------------------
// Kernel 1: MIC pair distances + truncated-Gaussian KDE histogram.
// Block b owns rows i=b and i=N-1-b (exactly N-1 pairs per block).
// Gaussian over the bin window evaluated by multiplicative recurrence:
//   g_{k+1} = g_k * t_k,  t_{k+1} = t_k * D,  D = exp(-(dr/w)^2)  (2 exps/pair)
// ---------------------------------------------------------------------------
__global__ void __launch_bounds__(256)
hist_kernel(const float* __restrict__ pos, const float* __restrict__ cell,
            const float* __restrict__ rb, int N, int nb) {
    __shared__ float s_hist[NB_MAX];
    __shared__ float s_r[NB_MAX];
    __shared__ float s_pos[NMAX * 3];
    __shared__ float s_ci[9];
    __shared__ float s_c[9];
    int t = threadIdx.x;

    for (int k = t; k < nb; k += 256) { s_hist[k] = 0.0f; s_r[k] = rb[k]; }
    for (int k = t; k < 3 * N; k += 256) s_pos[k] = pos[k];
    if (t < 9) { s_ci[t] = g_cinv[t]; s_c[t] = cell[t]; }
    __syncthreads();

    const float r0     = s_r[0];
    const float dr     = s_r[1] - s_r[0];
    const float inv_dr = 1.0f / dr;
    const float minb   = r0 - 3.0f * WKER;
    const float maxb   = s_r[nb - 1] + 3.0f * WKER;
    const float minb2  = (minb > 0.0f) ? minb * minb : -1.0f;
    const float maxb2  = maxb * maxb;
    const float delta  = dr * INV_WKER;               // bin step in sigma units
    const float Dfac   = __expf(-delta * delta);      // t ratio
    const float mh_d2  = -0.5f * delta * delta;
    const bool  diag   = (g_diag != 0);
    const float Lx = s_c[0], Ly = s_c[4], Lz = s_c[8];
    const float iLx = 1.0f / Lx, iLy = 1.0f / Ly, iLz = 1.0f / Lz;

    #pragma unroll
    for (int half = 0; half < 2; half++) {
        int i = (half == 0) ? (int)blockIdx.x : (N - 1 - (int)blockIdx.x);
        if (i < 0 || i >= N - 1) continue;
        float xi = s_pos[3*i + 0], yi = s_pos[3*i + 1], zi = s_pos[3*i + 2];

        for (int j = i + 1 + t; j < N; j += 256) {
            float dx = s_pos[3*j + 0] - xi;
            float dy = s_pos[3*j + 1] - yi;
            float dz = s_pos[3*j + 2] - zi;
            float d2;
            if (diag) {
                dx -= Lx * rintf(dx * iLx);
                dy -= Ly * rintf(dy * iLy);
                dz -= Lz * rintf(dz * iLz);
                d2 = dx*dx + dy*dy + dz*dz;
            } else {
                float fx = dx*s_ci[0] + dy*s_ci[3] + dz*s_ci[6];
                float fy = dx*s_ci[1] + dy*s_ci[4] + dz*s_ci[7];
                float fz = dx*s_ci[2] + dy*s_ci[5] + dz*s_ci[8];
                fx -= rintf(fx); fy -= rintf(fy); fz -= rintf(fz);
                float mx = fx*s_c[0] + fy*s_c[3] + fz*s_c[6];
                float my = fx*s_c[1] + fy*s_c[4] + fz*s_c[7];
                float mz = fx*s_c[2] + fy*s_c[5] + fz*s_c[8];
                d2 = mx*mx + my*my + mz*mz;
            }
            // exact window mask on d^2 (monotone equivalent of reference mask)
            if (d2 <= minb2 || d2 >= maxb2) continue;
            float d = sqrtf(d2 + 1e-10f);

            int klo = (int)ceilf ((d - CUT - r0) * inv_dr);
            int khi = (int)floorf((d + CUT - r0) * inv_dr);
            klo = klo < 0 ? 0 : klo;
            khi = khi > nb - 1 ? nb - 1 : khi;
            if (khi < klo) continue;

            float u  = (s_r[klo] - d) * INV_WKER;     // sigma units at klo
            float g  = GNORM * __expf(-0.5f * u * u);
            float tr = __expf(-u * delta + mh_d2);    // g_{k+1}/g_k at klo
            #pragma unroll 4
            for (int k = klo; k <= khi; k++) {
                atomicAdd(&s_hist[k], g);
                g  *= tr;
                tr *= Dfac;
            }
        }
    }
    __syncthreads();
    for (int k = t; k < nb; k += 256) {
        float v = s_hist[k];
        if (v != 0.0f) atomicAdd(&g_hist[k], v);
    }
}

// ---------------------------------------------------------------------------
// Kernel 2 (fused G + S + F):
//   Each block rebuilds G(r) and A_k = 4*pi*rho * w_k * r_k * G_k in shared
//   (w_k = trapezoid weights), block 0 also writes G to out.
//   S(Q) = 1 + (1/(Q+1e-10)) * sum_k A_k sin(Q r_k);  F(Q) = Q (S-1).
// ---------------------------------------------------------------------------
__global__ void __launch_bounds__(128)
sf_kernel(const float* __restrict__ rb, const float* __restrict__ qb,
          float* __restrict__ out, int nb, int N, float n_pairs) {
    __shared__ float sA[NB_MAX];
    __shared__ float sR[NB_MAX];
    __shared__ float s_red[4];
    int q = blockIdx.x;
    int t = threadIdx.x;

    float vol   = g_vol;
    float pref  = vol / n_pairs / (4.0f * PI_F);
    float coeff = 5.803f * 5.803f * 0.01f;
    float rho   = (float)N / vol;
    float rho4p = 4.0f * PI_F * rho;

    for (int k = t; k < nb; k += 128) {
        float r  = rb[k];
        float gp = pref * g_hist[k] / (r * r);
        float G  = coeff * (gp - 1.0f);
        if (q == 0) out[k] = G;
        float xm = (k > 0)      ? rb[k - 1] : r;
        float xp = (k < nb - 1) ? rb[k + 1] : r;
        sA[k] = rho4p * 0.5f * (xp - xm) * r * G;
        sR[k] = r;
    }
    __syncthreads();

    float Q    = qb[q];
    float invq = 1.0f / (Q + 1e-10f);
    float acc  = 0.0f;
    for (int k = t; k < nb; k += 128)
        acc += sA[k] * sinf(Q * sR[k]);

    #pragma unroll
    for (int o = 16; o > 0; o >>= 1)
        acc += __shfl_xor_sync(0xffffffff, acc, o);
    if ((t & 31) == 0) s_red[t >> 5] = acc;
    __syncthreads();
    if (t == 0) {
        float s = s_red[0] + s_red[1] + s_red[2] + s_red[3];
        float S = 1.0f + invq * s;
        out[nb + q]     = S;
        out[2 * nb + q] = Q * (S - 1.0f);
    }
}

// ---------------------------------------------------------------------------
extern "C" void kernel_launch(void* const* d_in, const int* in_sizes, int n_in,
                              void* d_out, int out_size) {
    const float* pos  = (const float*)d_in[0];
    const float* cell = (const float*)d_in[1];
    const float* rb   = (const float*)d_in[2];
    const float* qb   = (const float*)d_in[3];
    float* out = (float*)d_out;

    int N  = in_sizes[0] / 3;
    int nb = in_sizes[2];
    float n_pairs = 0.5f * (float)N * (float)(N - 1);

    setup_kernel<<<1, 512>>>(cell, nb);
    hist_kernel<<<(N + 1) / 2, 256>>>(pos, cell, rb, N, nb);
    sf_kernel<<<nb, 128>>>(rb, qb, out, nb, N, n_pairs);
}